// round 11
// baseline (speedup 1.0000x reference)
#include <cuda_runtime.h>
#include <cstdint>

#define NUM_B  4
#define SEQ    2048
#define DMODEL 1024
#define NH     16
#define DHEAD  64
#define MTOT   (NUM_B * SEQ)   // 8192

// ---------------------------------------------------------------------------
// Scratch (__device__ globals: allocation-free rule). All tf32-pre-rounded.
// ---------------------------------------------------------------------------
__device__ float g_q   [(size_t)NUM_B * NH * SEQ * DHEAD];   // [bh][s][d]
__device__ float g_k   [(size_t)NUM_B * NH * SEQ * DHEAD];   // [bh][s][d]
__device__ float g_vt  [(size_t)NUM_B * NH * DHEAD * SEQ];   // [bh][d][s]
__device__ float g_attn[(size_t)NUM_B * SEQ * DMODEL];       // [b][s][D]
__device__ float g_wt  [4ull * DMODEL * DMODEL];             // Wt[z][n][k]
__device__ float g_x   [3ull * MTOT * DMODEL];               // rounded inputs

// ---------------------------------------------------------------------------
__device__ __forceinline__ float tf32r(float x) {
    uint32_t u;
    asm("cvt.rna.tf32.f32 %0, %1;" : "=r"(u) : "f"(x));
    return __uint_as_float(u);
}

__device__ __forceinline__ void mma_tf32(float c[4], const float a[4], const float b[2]) {
    const uint32_t* A = reinterpret_cast<const uint32_t*>(a);
    const uint32_t* B = reinterpret_cast<const uint32_t*>(b);
    asm volatile(
        "mma.sync.aligned.m16n8k8.row.col.f32.tf32.tf32.f32 "
        "{%0,%1,%2,%3},{%4,%5,%6,%7},{%8,%9},{%0,%1,%2,%3};\n"
        : "+f"(c[0]), "+f"(c[1]), "+f"(c[2]), "+f"(c[3])
        : "r"(A[0]), "r"(A[1]), "r"(A[2]), "r"(A[3]), "r"(B[0]), "r"(B[1]));
}

// ---------------------------------------------------------------------------
// Pre-round inputs to tf32: g_x[z] = tf32r(x_z).  grid(8192,3), block 256.
// ---------------------------------------------------------------------------
__global__ void round_x_kernel(const float* __restrict__ xq,
                               const float* __restrict__ xk,
                               const float* __restrict__ xv)
{
    const int z = blockIdx.y;
    const float* src = (z == 0) ? xq : (z == 1) ? xk : xv;
    float* dst = g_x + (size_t)z * MTOT * DMODEL;
    const size_t i = (size_t)blockIdx.x * blockDim.x + threadIdx.x;   // float4 idx
    float4 v = ((const float4*)src)[i];
    v.x = tf32r(v.x); v.y = tf32r(v.y); v.z = tf32r(v.z); v.w = tf32r(v.w);
    ((float4*)dst)[i] = v;
}

// ---------------------------------------------------------------------------
// Weight transpose + tf32 round: g_wt[z][n][k] = tf32(W_z[k][n]).
// ---------------------------------------------------------------------------
__global__ void transpose_weights(const float* __restrict__ Wq, const float* __restrict__ Wk,
                                  const float* __restrict__ Wv, const float* __restrict__ Wo)
{
    __shared__ float tile[32][33];
    const float* W = (blockIdx.z == 0) ? Wq : (blockIdx.z == 1) ? Wk
                   : (blockIdx.z == 2) ? Wv : Wo;
    float* Wt = g_wt + (size_t)blockIdx.z * DMODEL * DMODEL;
    const int x0 = blockIdx.x * 32, y0 = blockIdx.y * 32;
    const int tx = threadIdx.x, ty = threadIdx.y;
#pragma unroll
    for (int r = 0; r < 32; r += 8)
        tile[ty + r][tx] = W[(size_t)(y0 + ty + r) * DMODEL + x0 + tx];
    __syncthreads();
#pragma unroll
    for (int r = 0; r < 32; r += 8)
        Wt[(size_t)(x0 + ty + r) * DMODEL + y0 + tx] = tf32r(tile[tx][ty + r]);
}

// ---------------------------------------------------------------------------
// tf32 GEMM mainloop: C(128x128) = A[128 x K] * Bt[128 x K]^T, K=1024.
// Sources pre-rounded -> staging is pure copy. A prefetched in regs, B direct.
// 256 thr, 8 warps (wM x wN = 4x2), warp tile 32x64. BK=32, dbl-buffered smem.
// smem row layout: (idx*2 + g)*24 + p,  p(k16) = (k16%4)*4 + k16/4.
// ---------------------------------------------------------------------------
#define GEMM_SMEM_BYTES (2 * 2 * 256 * 24 * 4)   // 98304

__device__ __forceinline__ void gemm_tc_body(
    const float* __restrict__ Ablk, const float* __restrict__ Btblk,
    float* sm, float (&acc)[2][8][4])
{
    const int t = threadIdx.x, lane = t & 31, wid = t >> 5;
    const int gid = lane >> 2, tig = lane & 3;
    const int wM = wid >> 1, wN = wid & 1;

    float4 ar[4];
    auto ldgA = [&](int k0) {
#pragma unroll
        for (int r = 0; r < 4; r++) {
            const int i = t + r * 256;
            const int m = i >> 3, kq = i & 7;
            ar[r] = *(const float4*)(Ablk + (size_t)m * DMODEL + k0 + kq * 4);
        }
    };
    ldgA(0);

    for (int k0 = 0; k0 < DMODEL; k0 += 32) {
        float* As = sm + ((k0 >> 5) & 1) * 12288;
        float* Bs = As + 6144;
#pragma unroll
        for (int r = 0; r < 4; r++) {
            const int i = t + r * 256;
            const int m = i >> 3, kq = i & 7;
            const int g = kq >> 2, q = kq & 3;
            float* d = As + (m * 2 + g) * 24 + q;
            d[0] = ar[r].x; d[4] = ar[r].y; d[8] = ar[r].z; d[12] = ar[r].w;
        }
#pragma unroll
        for (int r = 0; r < 4; r++) {
            const int i = t + r * 256;
            const int m = i >> 3, kq = i & 7;
            const float4 bv = *(const float4*)(Btblk + (size_t)m * DMODEL + k0 + kq * 4);
            const int g = kq >> 2, q = kq & 3;
            float* e = Bs + (m * 2 + g) * 24 + q;
            e[0] = bv.x; e[4] = bv.y; e[8] = bv.z; e[12] = bv.w;
        }
        __syncthreads();
        if (k0 + 32 < DMODEL) ldgA(k0 + 32);

#pragma unroll
        for (int g = 0; g < 2; g++) {
            float4 alo[2], ahi[2];
#pragma unroll
            for (int mi = 0; mi < 2; mi++) {
                const int r0 = wM * 32 + mi * 16 + gid;
                alo[mi] = *(const float4*)(As + (r0 * 2 + g) * 24 + tig * 4);
                ahi[mi] = *(const float4*)(As + ((r0 + 8) * 2 + g) * 24 + tig * 4);
            }
#pragma unroll
            for (int half = 0; half < 2; half++) {
                float4 bf[4];
#pragma unroll
                for (int n4 = 0; n4 < 4; n4++) {
                    const int n = wN * 64 + (half * 4 + n4) * 8 + gid;
                    bf[n4] = *(const float4*)(Bs + (n * 2 + g) * 24 + tig * 4);
                }
#pragma unroll
                for (int s = 0; s < 2; s++) {
                    float a[2][4];
#pragma unroll
                    for (int mi = 0; mi < 2; mi++) {
                        a[mi][0] = s ? alo[mi].z : alo[mi].x;
                        a[mi][1] = s ? ahi[mi].z : ahi[mi].x;
                        a[mi][2] = s ? alo[mi].w : alo[mi].y;
                        a[mi][3] = s ? ahi[mi].w : ahi[mi].y;
                    }
#pragma unroll
                    for (int n4 = 0; n4 < 4; n4++) {
                        float b2[2];
                        b2[0] = s ? bf[n4].z : bf[n4].x;
                        b2[1] = s ? bf[n4].w : bf[n4].y;
#pragma unroll
                        for (int mi = 0; mi < 2; mi++)
                            mma_tf32(acc[mi][half * 4 + n4], a[mi], b2);
                    }
                }
            }
        }
        __syncthreads();
    }
}

// ---------------------------------------------------------------------------
// Kernel 1: QKV projection. grid(8,64,3), block 256.
// Outputs tf32-rounded: sel 0/1 -> g_q/g_k [bh][s][d]; sel 2 -> g_vt [bh][d][s].
// ---------------------------------------------------------------------------
__global__ __launch_bounds__(256, 2)
void qkv_tc_kernel(const float* __restrict__ bq, const float* __restrict__ bk,
                   const float* __restrict__ bv)
{
    extern __shared__ float sm[];
    const int sel = blockIdx.z;
    const float* X    = g_x  + (size_t)sel * MTOT * DMODEL;
    const float* bias = (sel == 0) ? bq : (sel == 1) ? bk : bv;
    const float* Bt   = g_wt + (size_t)sel * DMODEL * DMODEL;

    const int rowBase = blockIdx.y * 128;
    const int colBase = blockIdx.x * 128;

    float acc[2][8][4];
#pragma unroll
    for (int mi = 0; mi < 2; mi++)
#pragma unroll
        for (int ni = 0; ni < 8; ni++)
#pragma unroll
            for (int e = 0; e < 4; e++) acc[mi][ni][e] = 0.f;

    gemm_tc_body(X + (size_t)rowBase * DMODEL, Bt + (size_t)colBase * DMODEL, sm, acc);

    const int t = threadIdx.x, lane = t & 31, wid = t >> 5;
    const int gid = lane >> 2, tig = lane & 3;
    const int wM = wid >> 1, wN = wid & 1;

#pragma unroll
    for (int mi = 0; mi < 2; mi++)
#pragma unroll
        for (int hh = 0; hh < 2; hh++) {
            const int r = rowBase + wM * 32 + mi * 16 + hh * 8 + gid;
            const int b = r >> 11, s = r & 2047;
#pragma unroll
            for (int ni = 0; ni < 8; ni++) {
                const int n = colBase + wN * 64 + ni * 8 + tig * 2;
                const float v0 = tf32r(acc[mi][ni][hh * 2 + 0] + bias[n + 0]);
                const float v1 = tf32r(acc[mi][ni][hh * 2 + 1] + bias[n + 1]);
                const int h = n >> 6, d = n & 63;
                if (sel == 2) {
                    float* vt = g_vt + (size_t)(b * NH + h) * DHEAD * SEQ;
                    vt[(size_t)d * SEQ + s]       = v0;
                    vt[(size_t)(d + 1) * SEQ + s] = v1;
                } else {
                    float* dst = ((sel == 0) ? g_q : g_k) +
                        ((size_t)(b * NH + h) * SEQ + s) * DHEAD + d;
                    *(float2*)dst = make_float2(v0, v1);
                }
            }
        }
}

// ---------------------------------------------------------------------------
// Kernel 2: flash attention. grid(32,64), block 128 (4 warps), 2 CTAs/SM.
// Warp tile = 16 q-rows x full 64 keys -> warp-private softmax (shfl 1,2).
// smem floats: Qs 5120 | Ks 5120 | Vs 5120 | Ps 5120 = 81920 B
// row layout: (idx*4 + g)*20 + p(k16); all sources pre-rounded tf32.
// ---------------------------------------------------------------------------
#define ATTN_SMEM_BYTES (4 * 5120 * 4)   // 81920

__global__ __launch_bounds__(128, 2)
void flash_tc_kernel(const int* __restrict__ mask)
{
    extern __shared__ float sm[];
    float* Qs = sm;
    float* Ks = sm + 5120;
    float* Vs = sm + 10240;
    float* Ps = sm + 15360;

    const int t = threadIdx.x, lane = t & 31, wid = t >> 5;   // wid 0..3
    const int gid = lane >> 2, tig = lane & 3;

    const int bh = blockIdx.y;
    const int b = bh >> 4, h = bh & 15;
    const int q0 = blockIdx.x * 64;

    const float* Qg = g_q  + ((size_t)bh * SEQ + q0) * DHEAD;
    const float* Kg = g_k  + (size_t)bh * SEQ * DHEAD;
    const float* Vt = g_vt + (size_t)bh * DHEAD * SEQ;

    // stage Q (scale by exact pow2 1/8; values already tf32)
#pragma unroll
    for (int r = 0; r < 8; r++) {
        const int i = t + r * 128;            // 1024 float4
        const int m = i >> 4, c = i & 15;
        float4 v = *(const float4*)(Qg + (size_t)m * DHEAD + c * 4);
        float* d = Qs + (m * 4 + (c >> 2)) * 20 + (c & 3);
        d[0] = v.x * 0.125f; d[4] = v.y * 0.125f;
        d[8] = v.z * 0.125f; d[12] = v.w * 0.125f;
    }

    float Ot[8][4], mrow[2], lrow[2];
#pragma unroll
    for (int nd = 0; nd < 8; nd++)
#pragma unroll
        for (int e = 0; e < 4; e++) Ot[nd][e] = 0.f;
    mrow[0] = mrow[1] = -1e30f;
    lrow[0] = lrow[1] = 0.f;

    for (int kt = 0; kt < SEQ / 64; kt++) {
        __syncthreads();   // prior tile's K/V reads done (covers Q staging on kt=0)
        const int kb2 = kt * 64;
#pragma unroll
        for (int r = 0; r < 8; r++) {
            const int i = t + r * 128;        // 1024 float4 each
            const int a = i >> 4, c = i & 15;
            const float4 kv = *(const float4*)(Kg + (size_t)(kb2 + a) * DHEAD + c * 4);
            const float4 vv = *(const float4*)(Vt + (size_t)a * SEQ + kb2 + c * 4);
            float* dk = Ks + (a * 4 + (c >> 2)) * 20 + (c & 3);
            dk[0] = kv.x; dk[4] = kv.y; dk[8] = kv.z; dk[12] = kv.w;
            float* dv = Vs + (a * 4 + (c >> 2)) * 20 + (c & 3);
            dv[0] = vv.x; dv[4] = vv.y; dv[8] = vv.z; dv[12] = vv.w;
        }
        __syncthreads();

        // ---- S = Q K^T : warp tile 16 rows x 64 keys ----
        float Sc[8][4];
#pragma unroll
        for (int ni = 0; ni < 8; ni++)
#pragma unroll
            for (int e = 0; e < 4; e++) Sc[ni][e] = 0.f;

#pragma unroll
        for (int g = 0; g < 4; g++) {
            const int r0 = wid * 16 + gid;
            float4 alo = *(const float4*)(Qs + (r0 * 4 + g) * 20 + tig * 4);
            float4 ahi = *(const float4*)(Qs + ((r0 + 8) * 4 + g) * 20 + tig * 4);
            float4 bf[8];
#pragma unroll
            for (int ni = 0; ni < 8; ni++) {
                const int n = ni * 8 + gid;
                bf[ni] = *(const float4*)(Ks + (n * 4 + g) * 20 + tig * 4);
            }
#pragma unroll
            for (int s = 0; s < 2; s++) {
                float a[4];
                a[0] = s ? alo.z : alo.x;
                a[1] = s ? ahi.z : ahi.x;
                a[2] = s ? alo.w : alo.y;
                a[3] = s ? ahi.w : ahi.y;
#pragma unroll
                for (int ni = 0; ni < 8; ni++) {
                    float b2[2];
                    b2[0] = s ? bf[ni].z : bf[ni].x;
                    b2[1] = s ? bf[ni].w : bf[ni].y;
                    mma_tf32(Sc[ni], a, b2);
                }
            }
        }

        // ---- mask + online softmax (row fully inside this warp's quad) ----
        const int kb = kt * 64;
#pragma unroll
        for (int hh = 0; hh < 2; hh++) {
            const int rloc = wid * 16 + hh * 8 + gid;
            const int grow = q0 + rloc;
            const int* mp = mask + ((size_t)b * SEQ + grow) * SEQ + kb;
            float sv[8][2];
            float mx = -1e30f;
#pragma unroll
            for (int ni = 0; ni < 8; ni++) {
                const int2 mv = *(const int2*)(mp + ni * 8 + tig * 2);
                const float s0 = (mv.x == 0) ? -1e9f : Sc[ni][hh * 2 + 0];
                const float s1 = (mv.y == 0) ? -1e9f : Sc[ni][hh * 2 + 1];
                sv[ni][0] = s0; sv[ni][1] = s1;
                mx = fmaxf(mx, fmaxf(s0, s1));
            }
            mx = fmaxf(mx, __shfl_xor_sync(0xffffffffu, mx, 1));
            mx = fmaxf(mx, __shfl_xor_sync(0xffffffffu, mx, 2));

            const float mold = mrow[hh];
            const float mnew = fmaxf(mold, mx);
            const float corr = __expf(mold - mnew);
            float sum = 0.f;
#pragma unroll
            for (int ni = 0; ni < 8; ni++) {
                const float p0 = __expf(sv[ni][0] - mnew);
                const float p1 = __expf(sv[ni][1] - mnew);
                sum += p0 + p1;
                const int c0 = ni * 8 + tig * 2;
                const int g = c0 >> 4;
                const int k16 = c0 & 15;
                Ps[(rloc * 4 + g) * 20 + (k16 & 3) * 4 + (k16 >> 2)]             = tf32r(p0);
                Ps[(rloc * 4 + g) * 20 + ((k16 + 1) & 3) * 4 + ((k16 + 1) >> 2)] = tf32r(p1);
            }
            sum += __shfl_xor_sync(0xffffffffu, sum, 1);
            sum += __shfl_xor_sync(0xffffffffu, sum, 2);
            lrow[hh] = lrow[hh] * corr + sum;
            mrow[hh] = mnew;
#pragma unroll
            for (int nd = 0; nd < 8; nd++) {
                Ot[nd][hh * 2 + 0] *= corr;
                Ot[nd][hh * 2 + 1] *= corr;
            }
        }
        __syncwarp();   // Ps rows are warp-private; cross-lane reads below

        // ---- O += P V : warp tile 16 rows x 64 d ----
#pragma unroll
        for (int g = 0; g < 4; g++) {
            const int r0 = wid * 16 + gid;
            float4 plo = *(const float4*)(Ps + (r0 * 4 + g) * 20 + tig * 4);
            float4 phi = *(const float4*)(Ps + ((r0 + 8) * 4 + g) * 20 + tig * 4);
            float4 bf[8];
#pragma unroll
            for (int nd = 0; nd < 8; nd++) {
                const int n = nd * 8 + gid;
                bf[nd] = *(const float4*)(Vs + (n * 4 + g) * 20 + tig * 4);
            }
#pragma unroll
            for (int s = 0; s < 2; s++) {
                float a[4];
                a[0] = s ? plo.z : plo.x;
                a[1] = s ? phi.z : phi.x;
                a[2] = s ? plo.w : plo.y;
                a[3] = s ? phi.w : phi.y;
#pragma unroll
                for (int nd = 0; nd < 8; nd++) {
                    float b2[2];
                    b2[0] = s ? bf[nd].z : bf[nd].x;
                    b2[1] = s ? bf[nd].w : bf[nd].y;
                    mma_tf32(Ot[nd], a, b2);
                }
            }
        }
    }

    // ---- normalize + write tf32-rounded to [b][s][h*64+d] ----
#pragma unroll
    for (int hh = 0; hh < 2; hh++) {
        const int rloc = wid * 16 + hh * 8 + gid;
        const int grow = q0 + rloc;
        const float inv = 1.0f / lrow[hh];
        float* op = g_attn + ((size_t)b * SEQ + grow) * DMODEL + h * DHEAD;
#pragma unroll
        for (int nd = 0; nd < 8; nd++) {
            const int d = nd * 8 + tig * 2;
            *(float2*)(op + d) = make_float2(tf32r(Ot[nd][hh * 2 + 0] * inv),
                                             tf32r(Ot[nd][hh * 2 + 1] * inv));
        }
    }
}

// ---------------------------------------------------------------------------
// Kernel 3: output projection. grid(8,64), block 256. fp32 output (no round).
// ---------------------------------------------------------------------------
__global__ __launch_bounds__(256, 2)
void out_tc_kernel(const float* __restrict__ bo, float* __restrict__ out)
{
    extern __shared__ float sm[];
    const float* Bt = g_wt + 3ull * DMODEL * DMODEL;
    const int rowBase = blockIdx.y * 128;
    const int colBase = blockIdx.x * 128;

    float acc[2][8][4];
#pragma unroll
    for (int mi = 0; mi < 2; mi++)
#pragma unroll
        for (int ni = 0; ni < 8; ni++)
#pragma unroll
            for (int e = 0; e < 4; e++) acc[mi][ni][e] = 0.f;

    gemm_tc_body(g_attn + (size_t)rowBase * DMODEL, Bt + (size_t)colBase * DMODEL, sm, acc);

    const int t = threadIdx.x, lane = t & 31, wid = t >> 5;
    const int gid = lane >> 2, tig = lane & 3;
    const int wM = wid >> 1, wN = wid & 1;

#pragma unroll
    for (int mi = 0; mi < 2; mi++)
#pragma unroll
        for (int hh = 0; hh < 2; hh++) {
            const int r = rowBase + wM * 32 + mi * 16 + hh * 8 + gid;
#pragma unroll
            for (int ni = 0; ni < 8; ni++) {
                const int n = colBase + wN * 64 + ni * 8 + tig * 2;
                *(float2*)(out + (size_t)r * DMODEL + n) =
                    make_float2(acc[mi][ni][hh * 2 + 0] + bo[n + 0],
                                acc[mi][ni][hh * 2 + 1] + bo[n + 1]);
            }
        }
}

// ---------------------------------------------------------------------------
extern "C" void kernel_launch(void* const* d_in, const int* in_sizes, int n_in,
                              void* d_out, int out_size)
{
    (void)in_sizes; (void)n_in; (void)out_size;
    const float* q_in = (const float*)d_in[0];
    const float* k_in = (const float*)d_in[1];
    const float* v_in = (const float*)d_in[2];
    const int*   mask = (const int*)d_in[3];
    const float* Wq = (const float*)d_in[4];
    const float* bq = (const float*)d_in[5];
    const float* Wk = (const float*)d_in[6];
    const float* bk = (const float*)d_in[7];
    const float* Wv = (const float*)d_in[8];
    const float* bv = (const float*)d_in[9];
    const float* Wo = (const float*)d_in[10];
    const float* bo = (const float*)d_in[11];
    float* out = (float*)d_out;

    cudaFuncSetAttribute(qkv_tc_kernel,
        cudaFuncAttributeMaxDynamicSharedMemorySize, GEMM_SMEM_BYTES);
    cudaFuncSetAttribute(out_tc_kernel,
        cudaFuncAttributeMaxDynamicSharedMemorySize, GEMM_SMEM_BYTES);
    cudaFuncSetAttribute(flash_tc_kernel,
        cudaFuncAttributeMaxDynamicSharedMemorySize, ATTN_SMEM_BYTES);

    round_x_kernel<<<dim3(MTOT * DMODEL / 4 / 256, 3), 256>>>(q_in, k_in, v_in);
    transpose_weights<<<dim3(32, 32, 4), dim3(32, 8)>>>(Wq, Wk, Wv, Wo);

    dim3 gP(DMODEL / 128, MTOT / 128, 3);
    qkv_tc_kernel<<<gP, 256, GEMM_SMEM_BYTES>>>(bq, bk, bv);

    dim3 gA(SEQ / 64, NUM_B * NH);
    flash_tc_kernel<<<gA, 128, ATTN_SMEM_BYTES>>>(mask);

    dim3 gO(DMODEL / 128, MTOT / 128);
    out_tc_kernel<<<gO, 256, GEMM_SMEM_BYTES>>>(bo, out);
}

// round 12
// speedup vs baseline: 1.0071x; 1.0071x over previous
#include <cuda_runtime.h>
#include <cstdint>

#define NUM_B  4
#define SEQ    2048
#define DMODEL 1024
#define NH     16
#define DHEAD  64
#define MTOT   (NUM_B * SEQ)   // 8192

// ---------------------------------------------------------------------------
// Scratch (__device__ globals: allocation-free rule). All tf32-pre-rounded.
// ---------------------------------------------------------------------------
__device__ float g_q   [(size_t)NUM_B * NH * SEQ * DHEAD];   // [bh][s][d]
__device__ float g_k   [(size_t)NUM_B * NH * SEQ * DHEAD];   // [bh][s][d]
__device__ float g_vt  [(size_t)NUM_B * NH * DHEAD * SEQ];   // [bh][d][s]
__device__ float g_attn[(size_t)NUM_B * SEQ * DMODEL];       // [b][s][D]
__device__ float g_wt  [4ull * DMODEL * DMODEL];             // Wt[z][n][k]
__device__ float g_x   [3ull * MTOT * DMODEL];               // rounded inputs

// ---------------------------------------------------------------------------
__device__ __forceinline__ float tf32r(float x) {
    uint32_t u;
    asm("cvt.rna.tf32.f32 %0, %1;" : "=r"(u) : "f"(x));
    return __uint_as_float(u);
}

__device__ __forceinline__ void mma_tf32(float c[4], const float a[4], const float b[2]) {
    const uint32_t* A = reinterpret_cast<const uint32_t*>(a);
    const uint32_t* B = reinterpret_cast<const uint32_t*>(b);
    asm volatile(
        "mma.sync.aligned.m16n8k8.row.col.f32.tf32.tf32.f32 "
        "{%0,%1,%2,%3},{%4,%5,%6,%7},{%8,%9},{%0,%1,%2,%3};\n"
        : "+f"(c[0]), "+f"(c[1]), "+f"(c[2]), "+f"(c[3])
        : "r"(A[0]), "r"(A[1]), "r"(A[2]), "r"(A[3]), "r"(B[0]), "r"(B[1]));
}

// ---------------------------------------------------------------------------
// Pre-round inputs to tf32.  grid(8192,3), block 256 (float4 per thread).
// ---------------------------------------------------------------------------
__global__ void round_x_kernel(const float* __restrict__ xq,
                               const float* __restrict__ xk,
                               const float* __restrict__ xv)
{
    const int z = blockIdx.y;
    const float* src = (z == 0) ? xq : (z == 1) ? xk : xv;
    float* dst = g_x + (size_t)z * MTOT * DMODEL;
    const size_t i = (size_t)blockIdx.x * blockDim.x + threadIdx.x;
    float4 v = ((const float4*)src)[i];
    v.x = tf32r(v.x); v.y = tf32r(v.y); v.z = tf32r(v.z); v.w = tf32r(v.w);
    ((float4*)dst)[i] = v;
}

// ---------------------------------------------------------------------------
// Weight transpose + tf32 round: g_wt[z][n][k] = tf32(W_z[k][n]).
// ---------------------------------------------------------------------------
__global__ void transpose_weights(const float* __restrict__ Wq, const float* __restrict__ Wk,
                                  const float* __restrict__ Wv, const float* __restrict__ Wo)
{
    __shared__ float tile[32][33];
    const float* W = (blockIdx.z == 0) ? Wq : (blockIdx.z == 1) ? Wk
                   : (blockIdx.z == 2) ? Wv : Wo;
    float* Wt = g_wt + (size_t)blockIdx.z * DMODEL * DMODEL;
    const int x0 = blockIdx.x * 32, y0 = blockIdx.y * 32;
    const int tx = threadIdx.x, ty = threadIdx.y;
#pragma unroll
    for (int r = 0; r < 32; r += 8)
        tile[ty + r][tx] = W[(size_t)(y0 + ty + r) * DMODEL + x0 + tx];
    __syncthreads();
#pragma unroll
    for (int r = 0; r < 32; r += 8)
        Wt[(size_t)(x0 + ty + r) * DMODEL + y0 + tx] = tf32r(tile[tx][ty + r]);
}

// ---------------------------------------------------------------------------
// tf32 GEMM mainloop (R10 structure): C(128x128)=A[128xK]*Bt[128xK]^T, K=1024.
// Both A and B register-prefetched; sources pre-rounded -> staging pure copy.
// 256 thr, 8 warps (4m x 2n), warp tile 32x64. BK=32, double-buffered smem.
// smem row layout: (idx*2 + g)*24 + p,  p(k16) = (k16%4)*4 + k16/4.
// ---------------------------------------------------------------------------
#define GEMM_SMEM_BYTES (2 * 2 * 256 * 24 * 4)   // 98304

__device__ __forceinline__ void gemm_tc_body(
    const float* __restrict__ Ablk, const float* __restrict__ Btblk,
    float* sm, float (&acc)[2][8][4])
{
    const int t = threadIdx.x, lane = t & 31, wid = t >> 5;
    const int gid = lane >> 2, tig = lane & 3;
    const int wM = wid >> 1, wN = wid & 1;

    float4 ar[4], br[4];
    auto ldg = [&](int k0) {
#pragma unroll
        for (int r = 0; r < 4; r++) {
            const int i = t + r * 256;
            const int m = i >> 3, kq = i & 7;
            ar[r] = *(const float4*)(Ablk  + (size_t)m * DMODEL + k0 + kq * 4);
            br[r] = *(const float4*)(Btblk + (size_t)m * DMODEL + k0 + kq * 4);
        }
    };
    ldg(0);

    for (int k0 = 0; k0 < DMODEL; k0 += 32) {
        float* As = sm + ((k0 >> 5) & 1) * 12288;
        float* Bs = As + 6144;
#pragma unroll
        for (int r = 0; r < 4; r++) {
            const int i = t + r * 256;
            const int m = i >> 3, kq = i & 7;
            const int g = kq >> 2, q = kq & 3;
            float* d = As + (m * 2 + g) * 24 + q;
            d[0] = ar[r].x; d[4] = ar[r].y; d[8] = ar[r].z; d[12] = ar[r].w;
            float* e = Bs + (m * 2 + g) * 24 + q;
            e[0] = br[r].x; e[4] = br[r].y; e[8] = br[r].z; e[12] = br[r].w;
        }
        __syncthreads();
        if (k0 + 32 < DMODEL) ldg(k0 + 32);

#pragma unroll
        for (int g = 0; g < 2; g++) {
            float4 alo[2], ahi[2], bf[8];
#pragma unroll
            for (int mi = 0; mi < 2; mi++) {
                const int r0 = wM * 32 + mi * 16 + gid;
                alo[mi] = *(const float4*)(As + (r0 * 2 + g) * 24 + tig * 4);
                ahi[mi] = *(const float4*)(As + ((r0 + 8) * 2 + g) * 24 + tig * 4);
            }
#pragma unroll
            for (int ni = 0; ni < 8; ni++) {
                const int n = wN * 64 + ni * 8 + gid;
                bf[ni] = *(const float4*)(Bs + (n * 2 + g) * 24 + tig * 4);
            }
#pragma unroll
            for (int s = 0; s < 2; s++) {
                float a[2][4];
#pragma unroll
                for (int mi = 0; mi < 2; mi++) {
                    a[mi][0] = s ? alo[mi].z : alo[mi].x;
                    a[mi][1] = s ? ahi[mi].z : ahi[mi].x;
                    a[mi][2] = s ? alo[mi].w : alo[mi].y;
                    a[mi][3] = s ? ahi[mi].w : ahi[mi].y;
                }
#pragma unroll
                for (int ni = 0; ni < 8; ni++) {
                    float b2[2];
                    b2[0] = s ? bf[ni].z : bf[ni].x;
                    b2[1] = s ? bf[ni].w : bf[ni].y;
#pragma unroll
                    for (int mi = 0; mi < 2; mi++)
                        mma_tf32(acc[mi][ni], a[mi], b2);
                }
            }
        }
        __syncthreads();
    }
}

// ---------------------------------------------------------------------------
// Kernel 1: QKV projection. grid(8,64,3), block 256.
// Outputs tf32-rounded: sel 0/1 -> g_q/g_k [bh][s][d]; sel 2 -> g_vt [bh][d][s].
// ---------------------------------------------------------------------------
__global__ __launch_bounds__(256)
void qkv_tc_kernel(const float* __restrict__ bq, const float* __restrict__ bk,
                   const float* __restrict__ bv)
{
    extern __shared__ float sm[];
    const int sel = blockIdx.z;
    const float* X    = g_x  + (size_t)sel * MTOT * DMODEL;
    const float* bias = (sel == 0) ? bq : (sel == 1) ? bk : bv;
    const float* Bt   = g_wt + (size_t)sel * DMODEL * DMODEL;

    const int rowBase = blockIdx.y * 128;
    const int colBase = blockIdx.x * 128;

    float acc[2][8][4];
#pragma unroll
    for (int mi = 0; mi < 2; mi++)
#pragma unroll
        for (int ni = 0; ni < 8; ni++)
#pragma unroll
            for (int e = 0; e < 4; e++) acc[mi][ni][e] = 0.f;

    gemm_tc_body(X + (size_t)rowBase * DMODEL, Bt + (size_t)colBase * DMODEL, sm, acc);

    const int t = threadIdx.x, lane = t & 31, wid = t >> 5;
    const int gid = lane >> 2, tig = lane & 3;
    const int wM = wid >> 1, wN = wid & 1;

#pragma unroll
    for (int mi = 0; mi < 2; mi++)
#pragma unroll
        for (int hh = 0; hh < 2; hh++) {
            const int r = rowBase + wM * 32 + mi * 16 + hh * 8 + gid;
            const int b = r >> 11, s = r & 2047;
#pragma unroll
            for (int ni = 0; ni < 8; ni++) {
                const int n = colBase + wN * 64 + ni * 8 + tig * 2;
                const float v0 = tf32r(acc[mi][ni][hh * 2 + 0] + bias[n + 0]);
                const float v1 = tf32r(acc[mi][ni][hh * 2 + 1] + bias[n + 1]);
                const int h = n >> 6, d = n & 63;
                if (sel == 2) {
                    float* vt = g_vt + (size_t)(b * NH + h) * DHEAD * SEQ;
                    vt[(size_t)d * SEQ + s]       = v0;
                    vt[(size_t)(d + 1) * SEQ + s] = v1;
                } else {
                    float* dst = ((sel == 0) ? g_q : g_k) +
                        ((size_t)(b * NH + h) * SEQ + s) * DHEAD + d;
                    *(float2*)dst = make_float2(v0, v1);
                }
            }
        }
}

// ---------------------------------------------------------------------------
// Kernel 2: flash attention. grid(8,64), block 256 (8 warps).
// Warp tile = 32 q-rows x full 64 keys -> 256 q-rows per CTA. This halves
// smem K/V fragment bytes per MAC vs the 16-row tile (L1 was 82% bound).
// Softmax stays warp-private (shfl xor 1,2 within quads).
// smem floats: Qs 20480 | Ks 5120 | Vs 5120 | Ps 20480 = 204800 B
// row layout: (idx*4 + g)*20 + p(k16); all sources pre-rounded tf32.
// ---------------------------------------------------------------------------
#define ATTN_SMEM_BYTES (51200 * 4)   // 204800

__global__ __launch_bounds__(256, 1)
void flash_tc_kernel(const int* __restrict__ mask)
{
    extern __shared__ float sm[];
    float* Qs = sm;               // 256 rows
    float* Ks = sm + 20480;       // 64 keys
    float* Vs = sm + 25600;       // 64 d-rows (of Vt)
    float* Ps = sm + 30720;       // 256 rows

    const int t = threadIdx.x, lane = t & 31, wid = t >> 5;   // wid 0..7
    const int gid = lane >> 2, tig = lane & 3;
    const int wr = wid * 32;                                   // warp row base

    const int bh = blockIdx.y;
    const int b = bh >> 4, h = bh & 15;
    const int q0 = blockIdx.x * 256;

    const float* Qg = g_q  + ((size_t)bh * SEQ + q0) * DHEAD;
    const float* Kg = g_k  + (size_t)bh * SEQ * DHEAD;
    const float* Vt = g_vt + (size_t)bh * DHEAD * SEQ;

    // stage Q (scale by exact pow2 1/8; values already tf32): 4096 float4
#pragma unroll
    for (int r = 0; r < 16; r++) {
        const int i = t + r * 256;
        const int m = i >> 4, c = i & 15;
        float4 v = *(const float4*)(Qg + (size_t)m * DHEAD + c * 4);
        float* d = Qs + (m * 4 + (c >> 2)) * 20 + (c & 3);
        d[0] = v.x * 0.125f; d[4] = v.y * 0.125f;
        d[8] = v.z * 0.125f; d[12] = v.w * 0.125f;
    }

    float Ot[2][8][4], mrow[2][2], lrow[2][2];
#pragma unroll
    for (int mi = 0; mi < 2; mi++) {
#pragma unroll
        for (int nd = 0; nd < 8; nd++)
#pragma unroll
            for (int e = 0; e < 4; e++) Ot[mi][nd][e] = 0.f;
        mrow[mi][0] = mrow[mi][1] = -1e30f;
        lrow[mi][0] = lrow[mi][1] = 0.f;
    }

    for (int kt = 0; kt < SEQ / 64; kt++) {
        __syncthreads();   // prior tile's K/V/P reads done (covers Q staging kt=0)
        const int kb2 = kt * 64;
#pragma unroll
        for (int r = 0; r < 4; r++) {
            const int i = t + r * 256;        // 1024 float4 each of K,V
            const int a = i >> 4, c = i & 15;
            const float4 kv = *(const float4*)(Kg + (size_t)(kb2 + a) * DHEAD + c * 4);
            const float4 vv = *(const float4*)(Vt + (size_t)a * SEQ + kb2 + c * 4);
            float* dk = Ks + (a * 4 + (c >> 2)) * 20 + (c & 3);
            dk[0] = kv.x; dk[4] = kv.y; dk[8] = kv.z; dk[12] = kv.w;
            float* dv = Vs + (a * 4 + (c >> 2)) * 20 + (c & 3);
            dv[0] = vv.x; dv[4] = vv.y; dv[8] = vv.z; dv[12] = vv.w;
        }
        __syncthreads();

        // ---- S = Q K^T : warp tile 32 rows x 64 keys ----
        float Sc[2][8][4];
#pragma unroll
        for (int mi = 0; mi < 2; mi++)
#pragma unroll
            for (int ni = 0; ni < 8; ni++)
#pragma unroll
                for (int e = 0; e < 4; e++) Sc[mi][ni][e] = 0.f;

#pragma unroll
        for (int g = 0; g < 4; g++) {
            float4 alo[2], ahi[2], bf[8];
#pragma unroll
            for (int mi = 0; mi < 2; mi++) {
                const int r0 = wr + mi * 16 + gid;
                alo[mi] = *(const float4*)(Qs + (r0 * 4 + g) * 20 + tig * 4);
                ahi[mi] = *(const float4*)(Qs + ((r0 + 8) * 4 + g) * 20 + tig * 4);
            }
#pragma unroll
            for (int ni = 0; ni < 8; ni++) {
                const int n = ni * 8 + gid;
                bf[ni] = *(const float4*)(Ks + (n * 4 + g) * 20 + tig * 4);
            }
#pragma unroll
            for (int s = 0; s < 2; s++) {
                float a[2][4];
#pragma unroll
                for (int mi = 0; mi < 2; mi++) {
                    a[mi][0] = s ? alo[mi].z : alo[mi].x;
                    a[mi][1] = s ? ahi[mi].z : ahi[mi].x;
                    a[mi][2] = s ? alo[mi].w : alo[mi].y;
                    a[mi][3] = s ? ahi[mi].w : ahi[mi].y;
                }
#pragma unroll
                for (int ni = 0; ni < 8; ni++) {
                    float b2[2];
                    b2[0] = s ? bf[ni].z : bf[ni].x;
                    b2[1] = s ? bf[ni].w : bf[ni].y;
#pragma unroll
                    for (int mi = 0; mi < 2; mi++)
                        mma_tf32(Sc[mi][ni], a[mi], b2);
                }
            }
        }

        // ---- mask + online softmax (rows fully inside this warp's quads) ----
        const int kb = kt * 64;
#pragma unroll
        for (int mi = 0; mi < 2; mi++)
#pragma unroll
            for (int hh = 0; hh < 2; hh++) {
                const int rloc = wr + mi * 16 + hh * 8 + gid;
                const int grow = q0 + rloc;
                const int* mp = mask + ((size_t)b * SEQ + grow) * SEQ + kb;
                float sv[8][2];
                float mx = -1e30f;
#pragma unroll
                for (int ni = 0; ni < 8; ni++) {
                    const int2 mv = *(const int2*)(mp + ni * 8 + tig * 2);
                    const float s0 = (mv.x == 0) ? -1e9f : Sc[mi][ni][hh * 2 + 0];
                    const float s1 = (mv.y == 0) ? -1e9f : Sc[mi][ni][hh * 2 + 1];
                    sv[ni][0] = s0; sv[ni][1] = s1;
                    mx = fmaxf(mx, fmaxf(s0, s1));
                }
                mx = fmaxf(mx, __shfl_xor_sync(0xffffffffu, mx, 1));
                mx = fmaxf(mx, __shfl_xor_sync(0xffffffffu, mx, 2));

                const float mold = mrow[mi][hh];
                const float mnew = fmaxf(mold, mx);
                const float corr = __expf(mold - mnew);
                float sum = 0.f;
#pragma unroll
                for (int ni = 0; ni < 8; ni++) {
                    const float p0 = __expf(sv[ni][0] - mnew);
                    const float p1 = __expf(sv[ni][1] - mnew);
                    sum += p0 + p1;
                    const int c0 = ni * 8 + tig * 2;
                    const int g = c0 >> 4;
                    const int k16 = c0 & 15;
                    Ps[(rloc * 4 + g) * 20 + (k16 & 3) * 4 + (k16 >> 2)]             = tf32r(p0);
                    Ps[(rloc * 4 + g) * 20 + ((k16 + 1) & 3) * 4 + ((k16 + 1) >> 2)] = tf32r(p1);
                }
                sum += __shfl_xor_sync(0xffffffffu, sum, 1);
                sum += __shfl_xor_sync(0xffffffffu, sum, 2);
                lrow[mi][hh] = lrow[mi][hh] * corr + sum;
                mrow[mi][hh] = mnew;
#pragma unroll
                for (int nd = 0; nd < 8; nd++) {
                    Ot[mi][nd][hh * 2 + 0] *= corr;
                    Ot[mi][nd][hh * 2 + 1] *= corr;
                }
            }
        __syncwarp();   // Ps rows are warp-private; cross-lane reads below

        // ---- O += P V : warp tile 32 rows x 64 d ----
#pragma unroll
        for (int g = 0; g < 4; g++) {
            float4 plo[2], phi[2], bf[8];
#pragma unroll
            for (int mi = 0; mi < 2; mi++) {
                const int r0 = wr + mi * 16 + gid;
                plo[mi] = *(const float4*)(Ps + (r0 * 4 + g) * 20 + tig * 4);
                phi[mi] = *(const float4*)(Ps + ((r0 + 8) * 4 + g) * 20 + tig * 4);
            }
#pragma unroll
            for (int nd = 0; nd < 8; nd++) {
                const int n = nd * 8 + gid;
                bf[nd] = *(const float4*)(Vs + (n * 4 + g) * 20 + tig * 4);
            }
#pragma unroll
            for (int s = 0; s < 2; s++) {
                float a[2][4];
#pragma unroll
                for (int mi = 0; mi < 2; mi++) {
                    a[mi][0] = s ? plo[mi].z : plo[mi].x;
                    a[mi][1] = s ? phi[mi].z : phi[mi].x;
                    a[mi][2] = s ? plo[mi].w : plo[mi].y;
                    a[mi][3] = s ? phi[mi].w : phi[mi].y;
                }
#pragma unroll
                for (int nd = 0; nd < 8; nd++) {
                    float b2[2];
                    b2[0] = s ? bf[nd].z : bf[nd].x;
                    b2[1] = s ? bf[nd].w : bf[nd].y;
#pragma unroll
                    for (int mi = 0; mi < 2; mi++)
                        mma_tf32(Ot[mi][nd], a[mi], b2);
                }
            }
        }
    }

    // ---- normalize + write tf32-rounded to [b][s][h*64+d] ----
#pragma unroll
    for (int mi = 0; mi < 2; mi++)
#pragma unroll
        for (int hh = 0; hh < 2; hh++) {
            const int rloc = wr + mi * 16 + hh * 8 + gid;
            const int grow = q0 + rloc;
            const float inv = 1.0f / lrow[mi][hh];
            float* op = g_attn + ((size_t)b * SEQ + grow) * DMODEL + h * DHEAD;
#pragma unroll
            for (int nd = 0; nd < 8; nd++) {
                const int d = nd * 8 + tig * 2;
                *(float2*)(op + d) = make_float2(tf32r(Ot[mi][nd][hh * 2 + 0] * inv),
                                                 tf32r(Ot[mi][nd][hh * 2 + 1] * inv));
            }
        }
}

// ---------------------------------------------------------------------------
// Kernel 3: output projection. grid(8,64), block 256. fp32 output.
// ---------------------------------------------------------------------------
__global__ __launch_bounds__(256)
void out_tc_kernel(const float* __restrict__ bo, float* __restrict__ out)
{
    extern __shared__ float sm[];
    const float* Bt = g_wt + 3ull * DMODEL * DMODEL;
    const int rowBase = blockIdx.y * 128;
    const int colBase = blockIdx.x * 128;

    float acc[2][8][4];
#pragma unroll
    for (int mi = 0; mi < 2; mi++)
#pragma unroll
        for (int ni = 0; ni < 8; ni++)
#pragma unroll
            for (int e = 0; e < 4; e++) acc[mi][ni][e] = 0.f;

    gemm_tc_body(g_attn + (size_t)rowBase * DMODEL, Bt + (size_t)colBase * DMODEL, sm, acc);

    const int t = threadIdx.x, lane = t & 31, wid = t >> 5;
    const int gid = lane >> 2, tig = lane & 3;
    const int wM = wid >> 1, wN = wid & 1;

#pragma unroll
    for (int mi = 0; mi < 2; mi++)
#pragma unroll
        for (int hh = 0; hh < 2; hh++) {
            const int r = rowBase + wM * 32 + mi * 16 + hh * 8 + gid;
#pragma unroll
            for (int ni = 0; ni < 8; ni++) {
                const int n = colBase + wN * 64 + ni * 8 + tig * 2;
                *(float2*)(out + (size_t)r * DMODEL + n) =
                    make_float2(acc[mi][ni][hh * 2 + 0] + bo[n + 0],
                                acc[mi][ni][hh * 2 + 1] + bo[n + 1]);
            }
        }
}

// ---------------------------------------------------------------------------
extern "C" void kernel_launch(void* const* d_in, const int* in_sizes, int n_in,
                              void* d_out, int out_size)
{
    (void)in_sizes; (void)n_in; (void)out_size;
    const float* q_in = (const float*)d_in[0];
    const float* k_in = (const float*)d_in[1];
    const float* v_in = (const float*)d_in[2];
    const int*   mask = (const int*)d_in[3];
    const float* Wq = (const float*)d_in[4];
    const float* bq = (const float*)d_in[5];
    const float* Wk = (const float*)d_in[6];
    const float* bk = (const float*)d_in[7];
    const float* Wv = (const float*)d_in[8];
    const float* bv = (const float*)d_in[9];
    const float* Wo = (const float*)d_in[10];
    const float* bo = (const float*)d_in[11];
    float* out = (float*)d_out;

    cudaFuncSetAttribute(qkv_tc_kernel,
        cudaFuncAttributeMaxDynamicSharedMemorySize, GEMM_SMEM_BYTES);
    cudaFuncSetAttribute(out_tc_kernel,
        cudaFuncAttributeMaxDynamicSharedMemorySize, GEMM_SMEM_BYTES);
    cudaFuncSetAttribute(flash_tc_kernel,
        cudaFuncAttributeMaxDynamicSharedMemorySize, ATTN_SMEM_BYTES);

    round_x_kernel<<<dim3(MTOT * DMODEL / 4 / 256, 3), 256>>>(q_in, k_in, v_in);
    transpose_weights<<<dim3(32, 32, 4), dim3(32, 8)>>>(Wq, Wk, Wv, Wo);

    dim3 gP(DMODEL / 128, MTOT / 128, 3);
    qkv_tc_kernel<<<gP, 256, GEMM_SMEM_BYTES>>>(bq, bk, bv);

    dim3 gA(SEQ / 256, NUM_B * NH);
    flash_tc_kernel<<<gA, 256, ATTN_SMEM_BYTES>>>(mask);

    dim3 gO(DMODEL / 128, MTOT / 128);
    out_tc_kernel<<<gO, 256, GEMM_SMEM_BYTES>>>(bo, out);
}

// round 13
// speedup vs baseline: 1.1814x; 1.1730x over previous
#include <cuda_runtime.h>
#include <cstdint>

#define NUM_B  4
#define SEQ    2048
#define DMODEL 1024
#define NH     16
#define DHEAD  64
#define MTOT   (NUM_B * SEQ)   // 8192

// ---------------------------------------------------------------------------
// Scratch (__device__ globals: allocation-free rule). Producer-side tf32.
// ---------------------------------------------------------------------------
__device__ float g_q   [(size_t)NUM_B * NH * SEQ * DHEAD];   // [bh][s][d]
__device__ float g_k   [(size_t)NUM_B * NH * SEQ * DHEAD];   // [bh][s][d]
__device__ float g_vt  [(size_t)NUM_B * NH * DHEAD * SEQ];   // [bh][d][s]
__device__ float g_attn[(size_t)NUM_B * SEQ * DMODEL];       // [b][s][D]
__device__ float g_wt  [4ull * DMODEL * DMODEL];             // Wt[z][n][k]

// ---------------------------------------------------------------------------
__device__ __forceinline__ float tf32r(float x) {
    uint32_t u;
    asm("cvt.rna.tf32.f32 %0, %1;" : "=r"(u) : "f"(x));
    return __uint_as_float(u);
}

__device__ __forceinline__ void mma_tf32(float c[4], const float a[4], const float b[2]) {
    const uint32_t* A = reinterpret_cast<const uint32_t*>(a);
    const uint32_t* B = reinterpret_cast<const uint32_t*>(b);
    asm volatile(
        "mma.sync.aligned.m16n8k8.row.col.f32.tf32.tf32.f32 "
        "{%0,%1,%2,%3},{%4,%5,%6,%7},{%8,%9},{%0,%1,%2,%3};\n"
        : "+f"(c[0]), "+f"(c[1]), "+f"(c[2]), "+f"(c[3])
        : "r"(A[0]), "r"(A[1]), "r"(A[2]), "r"(A[3]), "r"(B[0]), "r"(B[1]));
}

// ---------------------------------------------------------------------------
// Weight transpose + tf32 round: g_wt[z][n][k] = tf32(W_z[k][n]).
// ---------------------------------------------------------------------------
__global__ void transpose_weights(const float* __restrict__ Wq, const float* __restrict__ Wk,
                                  const float* __restrict__ Wv, const float* __restrict__ Wo)
{
    __shared__ float tile[32][33];
    const float* W = (blockIdx.z == 0) ? Wq : (blockIdx.z == 1) ? Wk
                   : (blockIdx.z == 2) ? Wv : Wo;
    float* Wt = g_wt + (size_t)blockIdx.z * DMODEL * DMODEL;
    const int x0 = blockIdx.x * 32, y0 = blockIdx.y * 32;
    const int tx = threadIdx.x, ty = threadIdx.y;
#pragma unroll
    for (int r = 0; r < 32; r += 8)
        tile[ty + r][tx] = W[(size_t)(y0 + ty + r) * DMODEL + x0 + tx];
    __syncthreads();
#pragma unroll
    for (int r = 0; r < 32; r += 8)
        Wt[(size_t)(x0 + ty + r) * DMODEL + y0 + tx] = tf32r(tile[tx][ty + r]);
}

// ---------------------------------------------------------------------------
// tf32 GEMM mainloop: C(128x128)=A[128xK]*Bt[128xK]^T, K=1024.
// CVTA: apply tf32r to A during staging (B always pre-rounded).
// 256 thr, 8 warps (4m x 2n), warp tile 32x64. BK=32, double-buffered smem.
// smem row layout: (idx*2 + g)*24 + p,  p(k16) = (k16%4)*4 + k16/4.
// ---------------------------------------------------------------------------
#define GEMM_SMEM_BYTES (2 * 2 * 256 * 24 * 4)   // 98304

template<bool CVTA>
__device__ __forceinline__ void gemm_tc_body(
    const float* __restrict__ Ablk, const float* __restrict__ Btblk,
    float* sm, float (&acc)[2][8][4])
{
    const int t = threadIdx.x, lane = t & 31, wid = t >> 5;
    const int gid = lane >> 2, tig = lane & 3;
    const int wM = wid >> 1, wN = wid & 1;

    float4 ar[4], br[4];
    auto ldg = [&](int k0) {
#pragma unroll
        for (int r = 0; r < 4; r++) {
            const int i = t + r * 256;
            const int m = i >> 3, kq = i & 7;
            ar[r] = *(const float4*)(Ablk  + (size_t)m * DMODEL + k0 + kq * 4);
            br[r] = *(const float4*)(Btblk + (size_t)m * DMODEL + k0 + kq * 4);
        }
    };
    ldg(0);

    for (int k0 = 0; k0 < DMODEL; k0 += 32) {
        float* As = sm + ((k0 >> 5) & 1) * 12288;
        float* Bs = As + 6144;
#pragma unroll
        for (int r = 0; r < 4; r++) {
            const int i = t + r * 256;
            const int m = i >> 3, kq = i & 7;
            const int g = kq >> 2, q = kq & 3;
            float* d = As + (m * 2 + g) * 24 + q;
            if (CVTA) {
                d[0] = tf32r(ar[r].x); d[4] = tf32r(ar[r].y);
                d[8] = tf32r(ar[r].z); d[12] = tf32r(ar[r].w);
            } else {
                d[0] = ar[r].x; d[4] = ar[r].y; d[8] = ar[r].z; d[12] = ar[r].w;
            }
            float* e = Bs + (m * 2 + g) * 24 + q;
            e[0] = br[r].x; e[4] = br[r].y; e[8] = br[r].z; e[12] = br[r].w;
        }
        __syncthreads();
        if (k0 + 32 < DMODEL) ldg(k0 + 32);

#pragma unroll
        for (int g = 0; g < 2; g++) {
            float4 alo[2], ahi[2], bf[8];
#pragma unroll
            for (int mi = 0; mi < 2; mi++) {
                const int r0 = wM * 32 + mi * 16 + gid;
                alo[mi] = *(const float4*)(As + (r0 * 2 + g) * 24 + tig * 4);
                ahi[mi] = *(const float4*)(As + ((r0 + 8) * 2 + g) * 24 + tig * 4);
            }
#pragma unroll
            for (int ni = 0; ni < 8; ni++) {
                const int n = wN * 64 + ni * 8 + gid;
                bf[ni] = *(const float4*)(Bs + (n * 2 + g) * 24 + tig * 4);
            }
#pragma unroll
            for (int s = 0; s < 2; s++) {
                float a[2][4];
#pragma unroll
                for (int mi = 0; mi < 2; mi++) {
                    a[mi][0] = s ? alo[mi].z : alo[mi].x;
                    a[mi][1] = s ? ahi[mi].z : ahi[mi].x;
                    a[mi][2] = s ? alo[mi].w : alo[mi].y;
                    a[mi][3] = s ? ahi[mi].w : ahi[mi].y;
                }
#pragma unroll
                for (int ni = 0; ni < 8; ni++) {
                    float b2[2];
                    b2[0] = s ? bf[ni].z : bf[ni].x;
                    b2[1] = s ? bf[ni].w : bf[ni].y;
#pragma unroll
                    for (int mi = 0; mi < 2; mi++)
                        mma_tf32(acc[mi][ni], a[mi], b2);
                }
            }
        }
        __syncthreads();
    }
}

// ---------------------------------------------------------------------------
// Kernel 1: QKV projection. grid(8,64,3), block 256.
// Outputs tf32-rounded: sel 0/1 -> g_q/g_k [bh][s][d]; sel 2 -> g_vt [bh][d][s].
// ---------------------------------------------------------------------------
__global__ __launch_bounds__(256)
void qkv_tc_kernel(const float* __restrict__ xq, const float* __restrict__ xk,
                   const float* __restrict__ xv,
                   const float* __restrict__ bq, const float* __restrict__ bk,
                   const float* __restrict__ bv)
{
    extern __shared__ float sm[];
    const int sel = blockIdx.z;
    const float* X    = (sel == 0) ? xq : (sel == 1) ? xk : xv;
    const float* bias = (sel == 0) ? bq : (sel == 1) ? bk : bv;
    const float* Bt   = g_wt + (size_t)sel * DMODEL * DMODEL;

    const int rowBase = blockIdx.y * 128;
    const int colBase = blockIdx.x * 128;

    float acc[2][8][4];
#pragma unroll
    for (int mi = 0; mi < 2; mi++)
#pragma unroll
        for (int ni = 0; ni < 8; ni++)
#pragma unroll
            for (int e = 0; e < 4; e++) acc[mi][ni][e] = 0.f;

    gemm_tc_body<true>(X + (size_t)rowBase * DMODEL, Bt + (size_t)colBase * DMODEL, sm, acc);

    const int t = threadIdx.x, lane = t & 31, wid = t >> 5;
    const int gid = lane >> 2, tig = lane & 3;
    const int wM = wid >> 1, wN = wid & 1;

#pragma unroll
    for (int mi = 0; mi < 2; mi++)
#pragma unroll
        for (int hh = 0; hh < 2; hh++) {
            const int r = rowBase + wM * 32 + mi * 16 + hh * 8 + gid;
            const int b = r >> 11, s = r & 2047;
#pragma unroll
            for (int ni = 0; ni < 8; ni++) {
                const int n = colBase + wN * 64 + ni * 8 + tig * 2;
                const float v0 = tf32r(acc[mi][ni][hh * 2 + 0] + bias[n + 0]);
                const float v1 = tf32r(acc[mi][ni][hh * 2 + 1] + bias[n + 1]);
                const int h = n >> 6, d = n & 63;
                if (sel == 2) {
                    float* vt = g_vt + (size_t)(b * NH + h) * DHEAD * SEQ;
                    vt[(size_t)d * SEQ + s]       = v0;
                    vt[(size_t)(d + 1) * SEQ + s] = v1;
                } else {
                    float* dst = ((sel == 0) ? g_q : g_k) +
                        ((size_t)(b * NH + h) * SEQ + s) * DHEAD + d;
                    *(float2*)dst = make_float2(v0, v1);
                }
            }
        }
}

// ---------------------------------------------------------------------------
// Kernel 2: flash attention. grid(16,64), block 256 (8 warps x 16 q-rows).
// P never touches smem: S C-fragments are converted to PV A-fragments with
// warp shuffles (lane mapping: a0=P[gid][tig] lives in lane 4*gid+(tig>>1),
// slot c0/c1 by parity; +2 lanes for the tig+4 column; c2/c3 for rows +8).
// K/V double-buffered; mask block L2-prefetched one pipeline-depth ahead.
// smem floats: Qs 10240 | Ks 2x5120 | Vs 2x5120 = 122880 B
// row layout: (idx*4 + g)*20 + p(k16), p = (k16%4)*4 + k16/4.
// ---------------------------------------------------------------------------
#define ATTN_SMEM_BYTES (30720 * 4)   // 122880

__global__ __launch_bounds__(256, 1)
void flash_tc_kernel(const int* __restrict__ mask)
{
    extern __shared__ float sm[];
    float* Qs = sm;               // 128 rows
    float* Ks = sm + 10240;       // 2 x 64 keys
    float* Vs = sm + 20480;       // 2 x 64 d-rows (of Vt)

    const int t = threadIdx.x, lane = t & 31, wid = t >> 5;   // wid 0..7
    const int gid = lane >> 2, tig = lane & 3;

    const int bh = blockIdx.y;
    const int b = bh >> 4, h = bh & 15;
    const int q0 = blockIdx.x * 128;

    const float* Qg = g_q  + ((size_t)bh * SEQ + q0) * DHEAD;
    const float* Kg = g_k  + (size_t)bh * SEQ * DHEAD;
    const float* Vt = g_vt + (size_t)bh * DHEAD * SEQ;
    const int* maskBase = mask + ((size_t)b * SEQ + q0) * SEQ;

    // stage Q (scale by exact pow2 1/8; values already tf32): 2048 float4
#pragma unroll
    for (int r = 0; r < 8; r++) {
        const int i = t + r * 256;
        const int m = i >> 4, c = i & 15;
        float4 v = *(const float4*)(Qg + (size_t)m * DHEAD + c * 4);
        float* d = Qs + (m * 4 + (c >> 2)) * 20 + (c & 3);
        d[0] = v.x * 0.125f; d[4] = v.y * 0.125f;
        d[8] = v.z * 0.125f; d[12] = v.w * 0.125f;
    }

    float Ot[8][4], mrow[2], lrow[2];
#pragma unroll
    for (int nd = 0; nd < 8; nd++)
#pragma unroll
        for (int e = 0; e < 4; e++) Ot[nd][e] = 0.f;
    mrow[0] = mrow[1] = -1e30f;
    lrow[0] = lrow[1] = 0.f;

    float4 kr[4], vr[4];
    auto preloadKV = [&](int kt) {
        const int kb2 = kt * 64;
#pragma unroll
        for (int r = 0; r < 4; r++) {
            const int i = t + r * 256;
            const int a = i >> 4, c = i & 15;
            kr[r] = *(const float4*)(Kg + (size_t)(kb2 + a) * DHEAD + c * 4);
            vr[r] = *(const float4*)(Vt + (size_t)a * SEQ + kb2 + c * 4);
        }
    };
    preloadKV(0);

    // shuffle source lanes for C->A fragment conversion (kt-invariant)
    const int s0lane = 4 * gid + (tig >> 1);
    const int s2lane = s0lane + 2;
    const bool podd = (tig & 1);

    for (int kt = 0; kt < SEQ / 64; kt++) {
        // L2-prefetch this tile's mask block (used ~1500 cyc later in softmax)
        {
            const int* pa = maskBase + (size_t)(t >> 1) * SEQ + kt * 64 + (t & 1) * 32;
            asm volatile("prefetch.global.L2 [%0];" :: "l"(pa));
        }

        float* Kb = Ks + (kt & 1) * 5120;
        float* Vb = Vs + (kt & 1) * 5120;
#pragma unroll
        for (int r = 0; r < 4; r++) {
            const int i = t + r * 256;
            const int a = i >> 4, c = i & 15;
            float* dk = Kb + (a * 4 + (c >> 2)) * 20 + (c & 3);
            dk[0] = kr[r].x; dk[4] = kr[r].y; dk[8] = kr[r].z; dk[12] = kr[r].w;
            float* dv = Vb + (a * 4 + (c >> 2)) * 20 + (c & 3);
            dv[0] = vr[r].x; dv[4] = vr[r].y; dv[8] = vr[r].z; dv[12] = vr[r].w;
        }
        __syncthreads();
        if (kt + 1 < SEQ / 64) preloadKV(kt + 1);

        // ---- S = Q K^T : warp tile 16 rows x 64 keys ----
        float Sc[8][4];
#pragma unroll
        for (int ni = 0; ni < 8; ni++)
#pragma unroll
            for (int e = 0; e < 4; e++) Sc[ni][e] = 0.f;

#pragma unroll
        for (int g = 0; g < 4; g++) {
            const int r0 = wid * 16 + gid;
            float4 alo = *(const float4*)(Qs + (r0 * 4 + g) * 20 + tig * 4);
            float4 ahi = *(const float4*)(Qs + ((r0 + 8) * 4 + g) * 20 + tig * 4);
            float4 bf[8];
#pragma unroll
            for (int ni = 0; ni < 8; ni++) {
                const int n = ni * 8 + gid;
                bf[ni] = *(const float4*)(Kb + (n * 4 + g) * 20 + tig * 4);
            }
#pragma unroll
            for (int s = 0; s < 2; s++) {
                float a[4];
                a[0] = s ? alo.z : alo.x;
                a[1] = s ? ahi.z : ahi.x;
                a[2] = s ? alo.w : alo.y;
                a[3] = s ? ahi.w : ahi.y;
#pragma unroll
                for (int ni = 0; ni < 8; ni++) {
                    float b2[2];
                    b2[0] = s ? bf[ni].z : bf[ni].x;
                    b2[1] = s ? bf[ni].w : bf[ni].y;
                    mma_tf32(Sc[ni], a, b2);
                }
            }
        }

        // ---- mask + online softmax; P overwrites Sc (tf32-rounded) ----
        const int kb = kt * 64;
#pragma unroll
        for (int hh = 0; hh < 2; hh++) {
            const int rloc = wid * 16 + hh * 8 + gid;
            const int* mp = maskBase + (size_t)rloc * SEQ + kb;
            float sv[8][2];
            float mx = -1e30f;
#pragma unroll
            for (int ni = 0; ni < 8; ni++) {
                const int2 mv = *(const int2*)(mp + ni * 8 + tig * 2);
                const float s0 = (mv.x == 0) ? -1e9f : Sc[ni][hh * 2 + 0];
                const float s1 = (mv.y == 0) ? -1e9f : Sc[ni][hh * 2 + 1];
                sv[ni][0] = s0; sv[ni][1] = s1;
                mx = fmaxf(mx, fmaxf(s0, s1));
            }
            mx = fmaxf(mx, __shfl_xor_sync(0xffffffffu, mx, 1));
            mx = fmaxf(mx, __shfl_xor_sync(0xffffffffu, mx, 2));

            const float mold = mrow[hh];
            const float mnew = fmaxf(mold, mx);
            const float corr = __expf(mold - mnew);
            float sum = 0.f;
#pragma unroll
            for (int ni = 0; ni < 8; ni++) {
                const float p0 = __expf(sv[ni][0] - mnew);
                const float p1 = __expf(sv[ni][1] - mnew);
                sum += p0 + p1;
                Sc[ni][hh * 2 + 0] = tf32r(p0);
                Sc[ni][hh * 2 + 1] = tf32r(p1);
            }
            sum += __shfl_xor_sync(0xffffffffu, sum, 1);
            sum += __shfl_xor_sync(0xffffffffu, sum, 2);
            lrow[hh] = lrow[hh] * corr + sum;
            mrow[hh] = mnew;
#pragma unroll
            for (int nd = 0; nd < 8; nd++) {
                Ot[nd][hh * 2 + 0] *= corr;
                Ot[nd][hh * 2 + 1] *= corr;
            }
        }

        // ---- O += P V : P C-frags -> A-frags via shuffles; V from smem ----
#pragma unroll
        for (int g = 0; g < 4; g++) {
            float4 bf[8];
#pragma unroll
            for (int nd = 0; nd < 8; nd++) {
                const int n = nd * 8 + gid;
                bf[nd] = *(const float4*)(Vb + (n * 4 + g) * 20 + tig * 4);
            }
#pragma unroll
            for (int s = 0; s < 2; s++) {
                const int kk = g * 2 + s;          // 8-key block = P c-frag index
                float a[4];
                {
                    const float x00 = __shfl_sync(0xffffffffu, Sc[kk][0], s0lane);
                    const float x01 = __shfl_sync(0xffffffffu, Sc[kk][1], s0lane);
                    const float x20 = __shfl_sync(0xffffffffu, Sc[kk][0], s2lane);
                    const float x21 = __shfl_sync(0xffffffffu, Sc[kk][1], s2lane);
                    a[0] = podd ? x01 : x00;
                    a[2] = podd ? x21 : x20;
                    const float y00 = __shfl_sync(0xffffffffu, Sc[kk][2], s0lane);
                    const float y01 = __shfl_sync(0xffffffffu, Sc[kk][3], s0lane);
                    const float y20 = __shfl_sync(0xffffffffu, Sc[kk][2], s2lane);
                    const float y21 = __shfl_sync(0xffffffffu, Sc[kk][3], s2lane);
                    a[1] = podd ? y01 : y00;
                    a[3] = podd ? y21 : y20;
                }
#pragma unroll
                for (int nd = 0; nd < 8; nd++) {
                    float b2[2];
                    b2[0] = s ? bf[nd].z : bf[nd].x;
                    b2[1] = s ? bf[nd].w : bf[nd].y;
                    mma_tf32(Ot[nd], a, b2);
                }
            }
        }
    }

    // ---- normalize + write tf32-rounded to [b][s][h*64+d] ----
#pragma unroll
    for (int hh = 0; hh < 2; hh++) {
        const int rloc = wid * 16 + hh * 8 + gid;
        const int grow = q0 + rloc;
        const float inv = 1.0f / lrow[hh];
        float* op = g_attn + ((size_t)b * SEQ + grow) * DMODEL + h * DHEAD;
#pragma unroll
        for (int nd = 0; nd < 8; nd++) {
            const int d = nd * 8 + tig * 2;
            *(float2*)(op + d) = make_float2(tf32r(Ot[nd][hh * 2 + 0] * inv),
                                             tf32r(Ot[nd][hh * 2 + 1] * inv));
        }
    }
}

// ---------------------------------------------------------------------------
// Kernel 3: output projection. grid(8,64), block 256. fp32 output.
// ---------------------------------------------------------------------------
__global__ __launch_bounds__(256)
void out_tc_kernel(const float* __restrict__ bo, float* __restrict__ out)
{
    extern __shared__ float sm[];
    const float* Bt = g_wt + 3ull * DMODEL * DMODEL;
    const int rowBase = blockIdx.y * 128;
    const int colBase = blockIdx.x * 128;

    float acc[2][8][4];
#pragma unroll
    for (int mi = 0; mi < 2; mi++)
#pragma unroll
        for (int ni = 0; ni < 8; ni++)
#pragma unroll
            for (int e = 0; e < 4; e++) acc[mi][ni][e] = 0.f;

    gemm_tc_body<false>(g_attn + (size_t)rowBase * DMODEL, Bt + (size_t)colBase * DMODEL, sm, acc);

    const int t = threadIdx.x, lane = t & 31, wid = t >> 5;
    const int gid = lane >> 2, tig = lane & 3;
    const int wM = wid >> 1, wN = wid & 1;

#pragma unroll
    for (int mi = 0; mi < 2; mi++)
#pragma unroll
        for (int hh = 0; hh < 2; hh++) {
            const int r = rowBase + wM * 32 + mi * 16 + hh * 8 + gid;
#pragma unroll
            for (int ni = 0; ni < 8; ni++) {
                const int n = colBase + wN * 64 + ni * 8 + tig * 2;
                *(float2*)(out + (size_t)r * DMODEL + n) =
                    make_float2(acc[mi][ni][hh * 2 + 0] + bo[n + 0],
                                acc[mi][ni][hh * 2 + 1] + bo[n + 1]);
            }
        }
}

// ---------------------------------------------------------------------------
extern "C" void kernel_launch(void* const* d_in, const int* in_sizes, int n_in,
                              void* d_out, int out_size)
{
    (void)in_sizes; (void)n_in; (void)out_size;
    const float* q_in = (const float*)d_in[0];
    const float* k_in = (const float*)d_in[1];
    const float* v_in = (const float*)d_in[2];
    const int*   mask = (const int*)d_in[3];
    const float* Wq = (const float*)d_in[4];
    const float* bq = (const float*)d_in[5];
    const float* Wk = (const float*)d_in[6];
    const float* bk = (const float*)d_in[7];
    const float* Wv = (const float*)d_in[8];
    const float* bv = (const float*)d_in[9];
    const float* Wo = (const float*)d_in[10];
    const float* bo = (const float*)d_in[11];
    float* out = (float*)d_out;

    cudaFuncSetAttribute(qkv_tc_kernel,
        cudaFuncAttributeMaxDynamicSharedMemorySize, GEMM_SMEM_BYTES);
    cudaFuncSetAttribute(out_tc_kernel,
        cudaFuncAttributeMaxDynamicSharedMemorySize, GEMM_SMEM_BYTES);
    cudaFuncSetAttribute(flash_tc_kernel,
        cudaFuncAttributeMaxDynamicSharedMemorySize, ATTN_SMEM_BYTES);

    transpose_weights<<<dim3(32, 32, 4), dim3(32, 8)>>>(Wq, Wk, Wv, Wo);

    dim3 gP(DMODEL / 128, MTOT / 128, 3);
    qkv_tc_kernel<<<gP, 256, GEMM_SMEM_BYTES>>>(q_in, k_in, v_in, bq, bk, bv);

    dim3 gA(SEQ / 128, NUM_B * NH);
    flash_tc_kernel<<<gA, 256, ATTN_SMEM_BYTES>>>(mask);

    dim3 gO(DMODEL / 128, MTOT / 128);
    out_tc_kernel<<<gO, 256, GEMM_SMEM_BYTES>>>(bo, out);
}

// round 15
// speedup vs baseline: 1.1938x; 1.0105x over previous
#include <cuda_runtime.h>
#include <cstdint>

#define NUM_B  4
#define SEQ    2048
#define DMODEL 1024
#define NH     16
#define DHEAD  64
#define MTOT   (NUM_B * SEQ)   // 8192

// ---------------------------------------------------------------------------
// Scratch (__device__ globals). All tf32-pre-rounded AND k-dim pre-permuted
// (within each 16-chunk: pos p holds k = perm(p), perm(p)=((p&3)<<2)|(p>>2),
// an involution). This makes gmem byte-identical to the smem tile layout so
// staging is pure cp.async 16B.
// ---------------------------------------------------------------------------
__device__ float g_q   [(size_t)NUM_B * NH * SEQ * DHEAD];   // [bh][s][d~] (x0.125)
__device__ float g_k   [(size_t)NUM_B * NH * SEQ * DHEAD];   // [bh][s][d~]
__device__ float g_vt  [(size_t)NUM_B * NH * DHEAD * SEQ];   // [bh][d][s~]
__device__ float g_attn[(size_t)NUM_B * SEQ * DMODEL];       // [b][s][D~]
__device__ float g_wt  [4ull * DMODEL * DMODEL];             // Wt[z][n][k~]
__device__ float g_x   [3ull * MTOT * DMODEL];               // x rounded+perm [m][k~]

// ---------------------------------------------------------------------------
__device__ __forceinline__ float tf32r(float x) {
    uint32_t u;
    asm("cvt.rna.tf32.f32 %0, %1;" : "=r"(u) : "f"(x));
    return __uint_as_float(u);
}
__device__ __forceinline__ int perm16(int v) { return ((v & 3) << 2) | (v >> 2); }

__device__ __forceinline__ void mma_tf32(float c[4], const float a[4], const float b[2]) {
    const uint32_t* A = reinterpret_cast<const uint32_t*>(a);
    const uint32_t* B = reinterpret_cast<const uint32_t*>(b);
    asm volatile(
        "mma.sync.aligned.m16n8k8.row.col.f32.tf32.tf32.f32 "
        "{%0,%1,%2,%3},{%4,%5,%6,%7},{%8,%9},{%0,%1,%2,%3};\n"
        : "+f"(c[0]), "+f"(c[1]), "+f"(c[2]), "+f"(c[3])
        : "r"(A[0]), "r"(A[1]), "r"(A[2]), "r"(A[3]), "r"(B[0]), "r"(B[1]));
}

__device__ __forceinline__ uint32_t smem_u32(const void* p) {
    return (uint32_t)__cvta_generic_to_shared(p);
}
__device__ __forceinline__ void cp16(uint32_t dst, const void* src) {
    asm volatile("cp.async.cg.shared.global [%0], [%1], 16;" :: "r"(dst), "l"(src));
}
#define CP_COMMIT() asm volatile("cp.async.commit_group;" ::: "memory")
#define CP_WAIT1()  asm volatile("cp.async.wait_group 1;" ::: "memory")
#define CP_WAIT0()  asm volatile("cp.async.wait_group 0;" ::: "memory")

// ---------------------------------------------------------------------------
// Pre-round + permute inputs: per 16-chunk transpose of 4 float4s.
// grid(2048,3), block 256, one 16-chunk per thread.
// ---------------------------------------------------------------------------
__global__ void round_perm_x(const float* __restrict__ xq,
                             const float* __restrict__ xk,
                             const float* __restrict__ xv)
{
    const int z = blockIdx.y;
    const float* src = (z == 0) ? xq : (z == 1) ? xk : xv;
    float* dst = g_x + (size_t)z * MTOT * DMODEL;
    const size_t chunk = (size_t)blockIdx.x * blockDim.x + threadIdx.x;
    const float4* s = (const float4*)src + chunk * 4;
    float4 i0 = s[0], i1 = s[1], i2 = s[2], i3 = s[3];
    float4* d = (float4*)dst + chunk * 4;
    d[0] = make_float4(tf32r(i0.x), tf32r(i1.x), tf32r(i2.x), tf32r(i3.x));
    d[1] = make_float4(tf32r(i0.y), tf32r(i1.y), tf32r(i2.y), tf32r(i3.y));
    d[2] = make_float4(tf32r(i0.z), tf32r(i1.z), tf32r(i2.z), tf32r(i3.z));
    d[3] = make_float4(tf32r(i0.w), tf32r(i1.w), tf32r(i2.w), tf32r(i3.w));
}

// ---------------------------------------------------------------------------
// Weight transpose + round + k-permute: g_wt[z][n][kpos] = tf32(W[perm(kpos)][n]).
// ---------------------------------------------------------------------------
__global__ void transpose_weights(const float* __restrict__ Wq, const float* __restrict__ Wk,
                                  const float* __restrict__ Wv, const float* __restrict__ Wo)
{
    __shared__ float tile[32][33];
    const float* W = (blockIdx.z == 0) ? Wq : (blockIdx.z == 1) ? Wk
                   : (blockIdx.z == 2) ? Wv : Wo;
    float* Wt = g_wt + (size_t)blockIdx.z * DMODEL * DMODEL;
    const int x0 = blockIdx.x * 32, y0 = blockIdx.y * 32;
    const int tx = threadIdx.x, ty = threadIdx.y;
#pragma unroll
    for (int r = 0; r < 32; r += 8)
        tile[ty + r][tx] = W[(size_t)(y0 + ty + r) * DMODEL + x0 + tx];
    __syncthreads();
    const int kl = (tx & ~15) | perm16(tx & 15);   // source k-local for dest col tx
#pragma unroll
    for (int r = 0; r < 32; r += 8)
        Wt[(size_t)(x0 + ty + r) * DMODEL + y0 + tx] = tf32r(tile[kl][ty + r]);
}

// ---------------------------------------------------------------------------
// tf32 GEMM mainloop: C(128x128)=A[128xK]*Bt[128xK]^T, K=1024. Sources are
// pre-rounded + pre-permuted -> staging is cp.async 16B, double-buffered.
// 256 thr, 8 warps (4m x 2n), warp tile 32x64. BK=32.
// smem row layout: (idx*2 + g)*24 + p.
// ---------------------------------------------------------------------------
#define GEMM_SMEM_BYTES (2 * 2 * 256 * 24 * 4)   // 98304

__device__ __forceinline__ void gemm_tc_body(
    const float* __restrict__ Ablk, const float* __restrict__ Btblk,
    float* sm, float (&acc)[2][8][4])
{
    const int t = threadIdx.x, lane = t & 31, wid = t >> 5;
    const int gid = lane >> 2, tig = lane & 3;
    const int wM = wid >> 1, wN = wid & 1;

    auto stage = [&](int k0, int buf) {
        float* As = sm + buf * 12288;
        float* Bs = As + 6144;
#pragma unroll
        for (int r = 0; r < 4; r++) {
            const int i = t + r * 256;
            const int m = i >> 3, kq = i & 7;
            const int off = (m * 2 + (kq >> 2)) * 24 + (kq & 3) * 4;
            cp16(smem_u32(As + off), Ablk  + (size_t)m * DMODEL + k0 + kq * 4);
            cp16(smem_u32(Bs + off), Btblk + (size_t)m * DMODEL + k0 + kq * 4);
        }
        CP_COMMIT();
    };
    stage(0, 0);

    for (int k0 = 0; k0 < DMODEL; k0 += 32) {
        const int buf = (k0 >> 5) & 1;
        if (k0 + 32 < DMODEL) { stage(k0 + 32, buf ^ 1); CP_WAIT1(); }
        else                  { CP_WAIT0(); }
        __syncthreads();

        float* As = sm + buf * 12288;
        float* Bs = As + 6144;
#pragma unroll
        for (int g = 0; g < 2; g++) {
            float4 alo[2], ahi[2], bf[8];
#pragma unroll
            for (int mi = 0; mi < 2; mi++) {
                const int r0 = wM * 32 + mi * 16 + gid;
                alo[mi] = *(const float4*)(As + (r0 * 2 + g) * 24 + tig * 4);
                ahi[mi] = *(const float4*)(As + ((r0 + 8) * 2 + g) * 24 + tig * 4);
            }
#pragma unroll
            for (int ni = 0; ni < 8; ni++) {
                const int n = wN * 64 + ni * 8 + gid;
                bf[ni] = *(const float4*)(Bs + (n * 2 + g) * 24 + tig * 4);
            }
#pragma unroll
            for (int s = 0; s < 2; s++) {
                float a[2][4];
#pragma unroll
                for (int mi = 0; mi < 2; mi++) {
                    a[mi][0] = s ? alo[mi].z : alo[mi].x;
                    a[mi][1] = s ? ahi[mi].z : ahi[mi].x;
                    a[mi][2] = s ? alo[mi].w : alo[mi].y;
                    a[mi][3] = s ? ahi[mi].w : ahi[mi].y;
                }
#pragma unroll
                for (int ni = 0; ni < 8; ni++) {
                    float b2[2];
                    b2[0] = s ? bf[ni].z : bf[ni].x;
                    b2[1] = s ? bf[ni].w : bf[ni].y;
#pragma unroll
                    for (int mi = 0; mi < 2; mi++)
                        mma_tf32(acc[mi][ni], a[mi], b2);
                }
            }
        }
        __syncthreads();
    }
}

// ---------------------------------------------------------------------------
// Kernel 1: QKV projection. grid(8,64,3), block 256, 2 CTAs/SM.
// Outputs tf32-rounded + permuted; Q additionally pre-scaled by 1/8 (exact).
// ---------------------------------------------------------------------------
__global__ __launch_bounds__(256, 2)
void qkv_tc_kernel(const float* __restrict__ bq, const float* __restrict__ bk,
                   const float* __restrict__ bv)
{
    extern __shared__ float sm[];
    const int sel = blockIdx.z;
    const float* X    = g_x  + (size_t)sel * MTOT * DMODEL;
    const float* bias = (sel == 0) ? bq : (sel == 1) ? bk : bv;
    const float* Bt   = g_wt + (size_t)sel * DMODEL * DMODEL;

    const int rowBase = blockIdx.y * 128;
    const int colBase = blockIdx.x * 128;

    float acc[2][8][4];
#pragma unroll
    for (int mi = 0; mi < 2; mi++)
#pragma unroll
        for (int ni = 0; ni < 8; ni++)
#pragma unroll
            for (int e = 0; e < 4; e++) acc[mi][ni][e] = 0.f;

    gemm_tc_body(X + (size_t)rowBase * DMODEL, Bt + (size_t)colBase * DMODEL, sm, acc);

    const int t = threadIdx.x, lane = t & 31, wid = t >> 5;
    const int gid = lane >> 2, tig = lane & 3;
    const int wM = wid >> 1, wN = wid & 1;
    const float scl = (sel == 0) ? 0.125f : 1.0f;

#pragma unroll
    for (int mi = 0; mi < 2; mi++)
#pragma unroll
        for (int hh = 0; hh < 2; hh++) {
            const int r = rowBase + wM * 32 + mi * 16 + hh * 8 + gid;
            const int b = r >> 11, s = r & 2047;
#pragma unroll
            for (int ni = 0; ni < 8; ni++) {
                const int n = colBase + wN * 64 + ni * 8 + tig * 2;   // even
                const float v0 = tf32r(acc[mi][ni][hh * 2 + 0] + bias[n + 0]) * scl;
                const float v1 = tf32r(acc[mi][ni][hh * 2 + 1] + bias[n + 1]) * scl;
                const int h = n >> 6, d = n & 63;
                if (sel == 2) {
                    float* vt = g_vt + (size_t)(b * NH + h) * DHEAD * SEQ;
                    const int sp = (s & ~15) | perm16(s & 15);        // permute s
                    vt[(size_t)d * SEQ + sp]       = v0;
                    vt[(size_t)(d + 1) * SEQ + sp] = v1;
                } else {
                    float* dst = ((sel == 0) ? g_q : g_k) +
                        ((size_t)(b * NH + h) * SEQ + s) * DHEAD;
                    const int p0 = perm16(d & 15);                    // permute d
                    dst[(d & ~15) + p0]     = v0;
                    dst[(d & ~15) + p0 + 4] = v1;
                }
            }
        }
}

// ---------------------------------------------------------------------------
// Kernel 2: flash attention. grid(16,64), block 256 (8 warps x 16 q-rows).
// cp.async staging (sources pre-permuted, Q pre-scaled); P kept in registers
// via shuffle C->A conversion; K/V double-buffered; mask L2-prefetched.
// smem floats: Qs 10240 | Ks 2x5120 | Vs 2x5120 = 122880 B
// ---------------------------------------------------------------------------
#define ATTN_SMEM_BYTES (30720 * 4)   // 122880

__global__ __launch_bounds__(256, 1)
void flash_tc_kernel(const int* __restrict__ mask)
{
    extern __shared__ float sm[];
    float* Qs = sm;               // 128 rows
    float* Ks = sm + 10240;       // 2 x 64 keys
    float* Vs = sm + 20480;       // 2 x 64 d-rows (of Vt)

    const int t = threadIdx.x, lane = t & 31, wid = t >> 5;   // wid 0..7
    const int gid = lane >> 2, tig = lane & 3;

    const int bh = blockIdx.y;
    const int b = bh >> 4, h = bh & 15;
    const int q0 = blockIdx.x * 128;

    const float* Qg = g_q  + ((size_t)bh * SEQ + q0) * DHEAD;
    const float* Kg = g_k  + (size_t)bh * SEQ * DHEAD;
    const float* Vt = g_vt + (size_t)bh * DHEAD * SEQ;
    const int* maskBase = mask + ((size_t)b * SEQ + q0) * SEQ;

    auto stageKV = [&](int kt, float* Kb, float* Vb) {
        const int kb2 = kt * 64;
#pragma unroll
        for (int r = 0; r < 4; r++) {
            const int i = t + r * 256;
            const int a = i >> 4, c = i & 15;
            const int off = (a * 4 + (c >> 2)) * 20 + (c & 3) * 4;
            cp16(smem_u32(Kb + off), Kg + (size_t)(kb2 + a) * DHEAD + c * 4);
            cp16(smem_u32(Vb + off), Vt + (size_t)a * SEQ + kb2 + c * 4);
        }
        CP_COMMIT();
    };

    // Q (already scaled+rounded+permuted) staged in group 0 with KV tile 0
#pragma unroll
    for (int r = 0; r < 8; r++) {
        const int i = t + r * 256;
        const int m = i >> 4, c = i & 15;
        cp16(smem_u32(Qs + (m * 4 + (c >> 2)) * 20 + (c & 3) * 4),
             Qg + (size_t)m * DHEAD + c * 4);
    }
    stageKV(0, Ks, Vs);

    float Ot[8][4], mrow[2], lrow[2];
#pragma unroll
    for (int nd = 0; nd < 8; nd++)
#pragma unroll
        for (int e = 0; e < 4; e++) Ot[nd][e] = 0.f;
    mrow[0] = mrow[1] = -1e30f;
    lrow[0] = lrow[1] = 0.f;

    const int s0lane = 4 * gid + (tig >> 1);
    const int s2lane = s0lane + 2;
    const bool podd = (tig & 1);

    for (int kt = 0; kt < SEQ / 64; kt++) {
        {
            const int* pa = maskBase + (size_t)(t >> 1) * SEQ + kt * 64 + (t & 1) * 32;
            asm volatile("prefetch.global.L2 [%0];" :: "l"(pa));
        }
        float* Kb = Ks + (kt & 1) * 5120;
        float* Vb = Vs + (kt & 1) * 5120;
        if (kt + 1 < SEQ / 64) {
            stageKV(kt + 1, Ks + ((kt + 1) & 1) * 5120, Vs + ((kt + 1) & 1) * 5120);
            CP_WAIT1();
        } else {
            CP_WAIT0();
        }
        __syncthreads();

        // ---- S = Q K^T : warp tile 16 rows x 64 keys ----
        float Sc[8][4];
#pragma unroll
        for (int ni = 0; ni < 8; ni++)
#pragma unroll
            for (int e = 0; e < 4; e++) Sc[ni][e] = 0.f;

#pragma unroll
        for (int g = 0; g < 4; g++) {
            const int r0 = wid * 16 + gid;
            float4 alo = *(const float4*)(Qs + (r0 * 4 + g) * 20 + tig * 4);
            float4 ahi = *(const float4*)(Qs + ((r0 + 8) * 4 + g) * 20 + tig * 4);
            float4 bf[8];
#pragma unroll
            for (int ni = 0; ni < 8; ni++) {
                const int n = ni * 8 + gid;
                bf[ni] = *(const float4*)(Kb + (n * 4 + g) * 20 + tig * 4);
            }
#pragma unroll
            for (int s = 0; s < 2; s++) {
                float a[4];
                a[0] = s ? alo.z : alo.x;
                a[1] = s ? ahi.z : ahi.x;
                a[2] = s ? alo.w : alo.y;
                a[3] = s ? ahi.w : ahi.y;
#pragma unroll
                for (int ni = 0; ni < 8; ni++) {
                    float b2[2];
                    b2[0] = s ? bf[ni].z : bf[ni].x;
                    b2[1] = s ? bf[ni].w : bf[ni].y;
                    mma_tf32(Sc[ni], a, b2);
                }
            }
        }

        // ---- mask + online softmax; P overwrites Sc (tf32-rounded) ----
        const int kb = kt * 64;
#pragma unroll
        for (int hh = 0; hh < 2; hh++) {
            const int rloc = wid * 16 + hh * 8 + gid;
            const int* mp = maskBase + (size_t)rloc * SEQ + kb;
            float sv[8][2];
            float mx = -1e30f;
#pragma unroll
            for (int ni = 0; ni < 8; ni++) {
                const int2 mv = *(const int2*)(mp + ni * 8 + tig * 2);
                const float s0 = (mv.x == 0) ? -1e9f : Sc[ni][hh * 2 + 0];
                const float s1 = (mv.y == 0) ? -1e9f : Sc[ni][hh * 2 + 1];
                sv[ni][0] = s0; sv[ni][1] = s1;
                mx = fmaxf(mx, fmaxf(s0, s1));
            }
            mx = fmaxf(mx, __shfl_xor_sync(0xffffffffu, mx, 1));
            mx = fmaxf(mx, __shfl_xor_sync(0xffffffffu, mx, 2));

            const float mold = mrow[hh];
            const float mnew = fmaxf(mold, mx);
            const float corr = __expf(mold - mnew);
            float sum = 0.f;
#pragma unroll
            for (int ni = 0; ni < 8; ni++) {
                const float p0 = __expf(sv[ni][0] - mnew);
                const float p1 = __expf(sv[ni][1] - mnew);
                sum += p0 + p1;
                Sc[ni][hh * 2 + 0] = tf32r(p0);
                Sc[ni][hh * 2 + 1] = tf32r(p1);
            }
            sum += __shfl_xor_sync(0xffffffffu, sum, 1);
            sum += __shfl_xor_sync(0xffffffffu, sum, 2);
            lrow[hh] = lrow[hh] * corr + sum;
            mrow[hh] = mnew;
#pragma unroll
            for (int nd = 0; nd < 8; nd++) {
                Ot[nd][hh * 2 + 0] *= corr;
                Ot[nd][hh * 2 + 1] *= corr;
            }
        }

        // ---- O += P V : P C-frags -> A-frags via shuffles; V from smem ----
#pragma unroll
        for (int g = 0; g < 4; g++) {
            float4 bf[8];
#pragma unroll
            for (int nd = 0; nd < 8; nd++) {
                const int n = nd * 8 + gid;
                bf[nd] = *(const float4*)(Vb + (n * 4 + g) * 20 + tig * 4);
            }
#pragma unroll
            for (int s = 0; s < 2; s++) {
                const int kk = g * 2 + s;
                float a[4];
                {
                    const float x00 = __shfl_sync(0xffffffffu, Sc[kk][0], s0lane);
                    const float x01 = __shfl_sync(0xffffffffu, Sc[kk][1], s0lane);
                    const float x20 = __shfl_sync(0xffffffffu, Sc[kk][0], s2lane);
                    const float x21 = __shfl_sync(0xffffffffu, Sc[kk][1], s2lane);
                    a[0] = podd ? x01 : x00;
                    a[2] = podd ? x21 : x20;
                    const float y00 = __shfl_sync(0xffffffffu, Sc[kk][2], s0lane);
                    const float y01 = __shfl_sync(0xffffffffu, Sc[kk][3], s0lane);
                    const float y20 = __shfl_sync(0xffffffffu, Sc[kk][2], s2lane);
                    const float y21 = __shfl_sync(0xffffffffu, Sc[kk][3], s2lane);
                    a[1] = podd ? y01 : y00;
                    a[3] = podd ? y21 : y20;
                }
#pragma unroll
                for (int nd = 0; nd < 8; nd++) {
                    float b2[2];
                    b2[0] = s ? bf[nd].z : bf[nd].x;
                    b2[1] = s ? bf[nd].w : bf[nd].y;
                    mma_tf32(Ot[nd], a, b2);
                }
            }
        }
        __syncthreads();
    }

    // ---- normalize + write tf32-rounded, D-permuted, to g_attn ----
#pragma unroll
    for (int hh = 0; hh < 2; hh++) {
        const int rloc = wid * 16 + hh * 8 + gid;
        const int grow = q0 + rloc;
        const float inv = 1.0f / lrow[hh];
        float* op = g_attn + ((size_t)b * SEQ + grow) * DMODEL + h * DHEAD;
#pragma unroll
        for (int nd = 0; nd < 8; nd++) {
            const int d = nd * 8 + tig * 2;                 // even
            const int p0 = perm16(d & 15);
            op[(d & ~15) + p0]     = tf32r(Ot[nd][hh * 2 + 0] * inv);
            op[(d & ~15) + p0 + 4] = tf32r(Ot[nd][hh * 2 + 1] * inv);
        }
    }
}

// ---------------------------------------------------------------------------
// Kernel 3: output projection. grid(8,64), block 256, 2 CTAs/SM. fp32 out.
// ---------------------------------------------------------------------------
__global__ __launch_bounds__(256, 2)
void out_tc_kernel(const float* __restrict__ bo, float* __restrict__ out)
{
    extern __shared__ float sm[];
    const float* Bt = g_wt + 3ull * DMODEL * DMODEL;
    const int rowBase = blockIdx.y * 128;
    const int colBase = blockIdx.x * 128;

    float acc[2][8][4];
#pragma unroll
    for (int mi = 0; mi < 2; mi++)
#pragma unroll
        for (int ni = 0; ni < 8; ni++)
#pragma unroll
            for (int e = 0; e < 4; e++) acc[mi][ni][e] = 0.f;

    gemm_tc_body(g_attn + (size_t)rowBase * DMODEL, Bt + (size_t)colBase * DMODEL, sm, acc);

    const int t = threadIdx.x, lane = t & 31, wid = t >> 5;
    const int gid = lane >> 2, tig = lane & 3;
    const int wM = wid >> 1, wN = wid & 1;

#pragma unroll
    for (int mi = 0; mi < 2; mi++)
#pragma unroll
        for (int hh = 0; hh < 2; hh++) {
            const int r = rowBase + wM * 32 + mi * 16 + hh * 8 + gid;
#pragma unroll
            for (int ni = 0; ni < 8; ni++) {
                const int n = colBase + wN * 64 + ni * 8 + tig * 2;
                *(float2*)(out + (size_t)r * DMODEL + n) =
                    make_float2(acc[mi][ni][hh * 2 + 0] + bo[n + 0],
                                acc[mi][ni][hh * 2 + 1] + bo[n + 1]);
            }
        }
}

// ---------------------------------------------------------------------------
extern "C" void kernel_launch(void* const* d_in, const int* in_sizes, int n_in,
                              void* d_out, int out_size)
{
    (void)in_sizes; (void)n_in; (void)out_size;
    const float* q_in = (const float*)d_in[0];
    const float* k_in = (const float*)d_in[1];
    const float* v_in = (const float*)d_in[2];
    const int*   mask = (const int*)d_in[3];
    const float* Wq = (const float*)d_in[4];
    const float* bq = (const float*)d_in[5];
    const float* Wk = (const float*)d_in[6];
    const float* bk = (const float*)d_in[7];
    const float* Wv = (const float*)d_in[8];
    const float* bv = (const float*)d_in[9];
    const float* Wo = (const float*)d_in[10];
    const float* bo = (const float*)d_in[11];
    float* out = (float*)d_out;

    cudaFuncSetAttribute(qkv_tc_kernel,
        cudaFuncAttributeMaxDynamicSharedMemorySize, GEMM_SMEM_BYTES);
    cudaFuncSetAttribute(out_tc_kernel,
        cudaFuncAttributeMaxDynamicSharedMemorySize, GEMM_SMEM_BYTES);
    cudaFuncSetAttribute(flash_tc_kernel,
        cudaFuncAttributeMaxDynamicSharedMemorySize, ATTN_SMEM_BYTES);

    round_perm_x<<<dim3(MTOT * DMODEL / 16 / 256, 3), 256>>>(q_in, k_in, v_in);
    transpose_weights<<<dim3(32, 32, 4), dim3(32, 8)>>>(Wq, Wk, Wv, Wo);

    dim3 gP(DMODEL / 128, MTOT / 128, 3);
    qkv_tc_kernel<<<gP, 256, GEMM_SMEM_BYTES>>>(bq, bk, bv);

    dim3 gA(SEQ / 128, NUM_B * NH);
    flash_tc_kernel<<<gA, 256, ATTN_SMEM_BYTES>>>(mask);

    dim3 gO(DMODEL / 128, MTOT / 128);
    out_tc_kernel<<<gO, 256, GEMM_SMEM_BYTES>>>(bo, out);
}